// round 11
// baseline (speedup 1.0000x reference)
#include <cuda_runtime.h>

#define Bg 256
#define Nn 128
#define Dd 128
#define Ll 32
#define Ee 262144
#define BNt 32768

__device__ float    g_z[BNt * Ll];           // 4 MB latents
__device__ unsigned g_cnt[BNt * 32];         // 4 MB packed byte multiplicities
__device__ float    g_W1T[Dd * Dd];          // pre-swizzled W1^T
__device__ float    g_wexp[Dd * Ll * 4];     // (wmu,wmu,wls,wls) per (k,l)
__device__ float    g_acc[2];                // [0]=sum log_probs, [1]=sum kls
__device__ int      g_is64;

// packed fp32 helpers ------------------------------------------------------
__device__ __forceinline__ void ffma2(unsigned long long& d,
                                      unsigned long long a, unsigned long long b) {
    asm("fma.rn.f32x2 %0, %1, %2, %3;" : "=l"(d) : "l"(a), "l"(b), "l"(d));
}
__device__ __forceinline__ float2 unpack2(unsigned long long v) {
    float lo, hi;
    asm("mov.b64 {%0, %1}, %2;" : "=f"(lo), "=f"(hi) : "l"(v));
    return make_float2(lo, hi);
}

// ---------------------------------------------------------------------------
__global__ void k_init(const void* ei) {
    int i = blockIdx.x * blockDim.x + threadIdx.x;
    int stride = gridDim.x * blockDim.x;
    uint4 z4 = make_uint4(0u, 0u, 0u, 0u);
    for (int j = i; j < BNt * 32 / 4; j += stride) ((uint4*)g_cnt)[j] = z4;
    if (i < 2) g_acc[i] = 0.f;
    if (i == 0) {
        const int* e32 = (const int*)ei;
        int all0 = 1;
        #pragma unroll
        for (int t = 0; t < 32; t++) all0 &= (e32[2 * t + 1] == 0);
        g_is64 = all0;
    }
}

__device__ __forceinline__ void load_edge(const void* ei, int e, int& s, int& d) {
    if (g_is64) {
        s = (int)((const long long*)ei)[e];
        d = (int)((const long long*)ei)[Ee + e];
    } else {
        s = ((const int*)ei)[e];
        d = ((const int*)ei)[Ee + e];
    }
}

// per-edge multiplicity counts, packed 4 bytes/word (no-return atomics)
__global__ void k_count(const void* __restrict__ ei) {
    int e = blockIdx.x * blockDim.x + threadIdx.x;
    if (e >= Ee) return;
    int s, d; load_edge(ei, e, s, d);
    int b = s >> 7, li = s & (Nn - 1), lj = d & (Nn - 1);
    atomicAdd(&g_cnt[(b * Nn + li) * 32 + (lj >> 2)], 1u << (8 * (lj & 3)));
    atomicAdd(&g_cnt[(b * Nn + lj) * 32 + (li >> 2)], 1u << (8 * (li & 3)));
}

// one-shot weight prep: swizzled W1^T + duplicated-interleaved mu/ls weights
__global__ void k_prep(const float* __restrict__ W1, const float* __restrict__ Wmu,
                       const float* __restrict__ Wls) {
    int i = blockIdx.x * blockDim.x + threadIdx.x;   // 0..16383
    {
        // inverse of: (k,c) -> ((c*32 + (((k>>2)+(c>>2))&31))*4 + (k&3))
        int low2 = i & 3;
        int f4i  = i >> 2;
        int c    = f4i >> 5;
        int g4   = f4i & 31;
        int k    = (((g4 - (c >> 2)) & 31) << 2) + low2;
        g_W1T[i] = W1[k * Dd + c];
    }
    if (i < Dd * Ll) {
        float wm = Wmu[i], wl = Wls[i];
        ((float4*)g_wexp)[i] = make_float4(wm, wm, wl, wl);
    }
}

// block reduce (16 warps)
__device__ __forceinline__ float block_reduce16(float v) {
    __shared__ float sred[16];
    int lane = threadIdx.x & 31, w = threadIdx.x >> 5;
    #pragma unroll
    for (int o = 16; o; o >>= 1) v += __shfl_down_sync(0xffffffffu, v, o);
    if (lane == 0) sred[w] = v;
    __syncthreads();
    v = (threadIdx.x < 16) ? sred[threadIdx.x] : 0.f;
    if (w == 0) {
        #pragma unroll
        for (int o = 8; o; o >>= 1) v += __shfl_down_sync(0xffffffffu, v, o);
    }
    return v;  // valid in thread 0
}

// ---------------------------------------------------------------------------
// fused encoder: CTA = one graph, 512 threads, 208KB smem
// shX: x -> H2 (row-pair interleaved) ; shW: W1T -> wexp ; shH: T ; shC counts
// ---------------------------------------------------------------------------
__global__ void __launch_bounds__(512)
k_enc(const float* __restrict__ x, const float* __restrict__ b1,
      const float* __restrict__ bmu, const float* __restrict__ bls,
      const float* __restrict__ eps) {
    extern __shared__ float sm[];
    float* shX = sm;             // 16384 floats
    float* shW = sm + 16384;     // 16384 floats
    float* shH = sm + 32768;     // 16384 floats
    unsigned* shC = (unsigned*)(sm + 49152);  // 4096 words (16KB)
    const int tid = threadIdx.x;
    const int b = blockIdx.x;
    const int lane = tid & 31;

    // load weights + x tile + count table (all independent)
    {
        const float4* wt = (const float4*)g_W1T;
        const float4* xg = (const float4*)(x + (size_t)b * Nn * Dd);
        const uint4*  cg = (const uint4*)g_cnt + b * 1024;
        float4* w4 = (float4*)shW;
        float4* x4 = (float4*)shX;
        uint4*  c4 = (uint4*)shC;
        for (int i = tid; i < 4096; i += 512) { w4[i] = wt[i]; x4[i] = xg[i]; }
        for (int i = tid; i < 1024; i += 512) c4[i] = cg[i];
    }
    __syncthreads();

    // gather: warp per node (16 warps x 8 nodes), multiplicity-weighted
    {
        const float4* x4 = (const float4*)shX;
        float4* t4 = (float4*)shH;
        int wi = tid >> 5;
        for (int t = 0; t < 8; t++) {
            int n = wi * 8 + t;
            float4 acc = x4[n * 32 + lane];
            #pragma unroll 4
            for (int w = 0; w < 32; w++) {
                unsigned cw = shC[n * 32 + w];   // broadcast LDS, uniform
                if (!cw) continue;
                #pragma unroll
                for (int b4 = 0; b4 < 4; b4++) {
                    unsigned cnt = (cw >> (8 * b4)) & 255u;
                    if (cnt) {
                        float fc = (float)cnt;
                        float4 xv = x4[(w * 4 + b4) * 32 + lane];
                        acc.x += fc * xv.x; acc.y += fc * xv.y;
                        acc.z += fc * xv.z; acc.w += fc * xv.w;
                    }
                }
            }
            t4[n * 32 + lane] = acc;
        }
    }
    __syncthreads();

    // phase1: H = relu(T @ W1 + b1); f32x2 paired along k
    // store H row-pair interleaved into shX: shX[(rp*128 + col)*2 + (r&1)]
    {
        const int tx = tid & 31;          // f4 col group -> cols 4tx..4tx+3
        const int rg = (tid >> 5) * 8;    // 8 rows
        const ulonglong2* tW = (const ulonglong2*)shW;
        const ulonglong2* tT = (const ulonglong2*)shH;
        unsigned long long acc[8][4];
        #pragma unroll
        for (int i = 0; i < 8; i++)
            #pragma unroll
            for (int c = 0; c < 4; c++) acc[i][c] = 0ull;

        for (int k4 = 0; k4 < 32; k4++) {
            ulonglong2 w2[4];
            int gp = (k4 + tx) & 31;
            #pragma unroll
            for (int cc = 0; cc < 4; cc++) w2[cc] = tW[(4 * tx + cc) * 32 + gp];
            #pragma unroll
            for (int i = 0; i < 8; i++) {
                ulonglong2 a2 = tT[(rg + i) * 32 + k4];
                #pragma unroll
                for (int cc = 0; cc < 4; cc++) {
                    ffma2(acc[i][cc], a2.x, w2[cc].x);
                    ffma2(acc[i][cc], a2.y, w2[cc].y);
                }
            }
        }
        float4 bb = *(const float4*)(b1 + tx * 4);
        float bv[4] = {bb.x, bb.y, bb.z, bb.w};
        #pragma unroll
        for (int i = 0; i < 8; i++) {
            int r = rg + i, rp = r >> 1, half = r & 1;
            #pragma unroll
            for (int cc = 0; cc < 4; cc++) {
                float2 p = unpack2(acc[i][cc]);
                float hv = fmaxf(p.x + p.y + bv[cc], 0.f);
                shX[((rp * 128) + (4 * tx + cc)) * 2 + half] = hv;
            }
        }
    }
    __syncthreads();

    // load duplicated (wmu,wmu,wls,wls) table over W1T
    {
        const float4* we = (const float4*)g_wexp;
        float4* w4 = (float4*)shW;
        for (int i = tid; i < 4096; i += 512) w4[i] = we[i];
    }
    __syncthreads();

    // phase2: thread = row-pair rp (64) x latent group lg (8 -> 4 l each)
    float klp = 0.f;
    {
        const int lg = tid & 7, rp = tid >> 3;
        const int l0 = lg * 4;
        const unsigned long long* h2 = (const unsigned long long*)shX;
        const ulonglong2* wv = (const ulonglong2*)shW;
        unsigned long long amu[4], als[4];
        #pragma unroll
        for (int j = 0; j < 4; j++) { amu[j] = 0ull; als[j] = 0ull; }

        #pragma unroll 4
        for (int k = 0; k < 128; k++) {
            unsigned long long hp = h2[rp * 128 + k];   // (h_r0, h_r1)
            #pragma unroll
            for (int j = 0; j < 4; j++) {
                ulonglong2 w = wv[k * 32 + l0 + j];     // ((wmu,wmu),(wls,wls))
                ffma2(amu[j], hp, w.x);
                ffma2(als[j], hp, w.y);
            }
        }
        float4 bm = *(const float4*)(bmu + l0);
        float4 bl = *(const float4*)(bls + l0);
        float bmv[4] = {bm.x, bm.y, bm.z, bm.w};
        float blv[4] = {bl.x, bl.y, bl.z, bl.w};
        int row0 = b * Nn + rp * 2;
        float4 e0 = *(const float4*)(eps + row0 * Ll + l0);
        float4 e1 = *(const float4*)(eps + (row0 + 1) * Ll + l0);
        float ev0[4] = {e0.x, e0.y, e0.z, e0.w};
        float ev1[4] = {e1.x, e1.y, e1.z, e1.w};
        float z0[4], z1[4];
        #pragma unroll
        for (int j = 0; j < 4; j++) {
            float2 pm = unpack2(amu[j]);
            float2 pl = unpack2(als[j]);
            float m0 = pm.x + bmv[j], m1 = pm.y + bmv[j];
            float s0 = pl.x + blv[j], s1 = pl.y + blv[j];
            float st0 = __expf(s0), st1 = __expf(s1);
            z0[j] = m0 + st0 * ev0[j];
            z1[j] = m1 + st1 * ev1[j];
            klp += 0.5f * (st0 * st0 + m0 * m0 - 1.f - 2.f * s0)
                 + 0.5f * (st1 * st1 + m1 * m1 - 1.f - 2.f * s1);
        }
        *(float4*)(g_z + row0 * Ll + l0)       = make_float4(z0[0], z0[1], z0[2], z0[3]);
        *(float4*)(g_z + (row0 + 1) * Ll + l0) = make_float4(z1[0], z1[1], z1[2], z1[3]);
    }
    float tot = block_reduce16(klp);
    if (tid == 0) atomicAdd(&g_acc[1], tot);
}

// ---------------------------------------------------------------------------
// decoder: CTA = graph, 512 threads, f32x2 gram; targets = (count != 0)
// ---------------------------------------------------------------------------
__global__ void __launch_bounds__(512) k_dec() {
    __shared__ float shZ[Nn * 32];
    __shared__ unsigned char shC[Nn * Nn];   // 16KB count bytes
    const int tid = threadIdx.x;
    const int b = blockIdx.x;

    {
        const float4* zg = (const float4*)(g_z + (size_t)b * Nn * Ll);
        float4* z4 = (float4*)shZ;
        for (int j = tid; j < 1024; j += 512) {
            int n = j >> 3, k4 = j & 7;
            z4[n * 8 + ((k4 + (n >> 3)) & 7)] = zg[j];
        }
        const uint4* cg = (const uint4*)g_cnt + b * 1024;
        uint4* c4 = (uint4*)shC;
        for (int i = tid; i < 1024; i += 512) c4[i] = cg[i];
    }
    __syncthreads();

    const int tx = tid & 15, ty = tid >> 4;
    const int r0 = ty * 4, c0 = tx * 8;
    const int rota = ty >> 1;
    const ulonglong2* z2 = (const ulonglong2*)shZ;

    unsigned long long acc[4][8];
    #pragma unroll
    for (int i = 0; i < 4; i++)
        #pragma unroll
        for (int j = 0; j < 8; j++) acc[i][j] = 0ull;

    #pragma unroll
    for (int k4 = 0; k4 < 8; k4++) {
        ulonglong2 bb[8];
        int gb = (k4 + tx) & 7;
        #pragma unroll
        for (int j = 0; j < 8; j++) bb[j] = z2[(c0 + j) * 8 + gb];
        int ga = (k4 + rota) & 7;
        #pragma unroll
        for (int i = 0; i < 4; i++) {
            ulonglong2 a2 = z2[(r0 + i) * 8 + ga];
            #pragma unroll
            for (int j = 0; j < 8; j++) {
                ffma2(acc[i][j], a2.x, bb[j].x);
                ffma2(acc[i][j], a2.y, bb[j].y);
            }
        }
    }

    float lp = 0.f;
    #pragma unroll
    for (int i = 0; i < 4; i++) {
        int r = r0 + i;
        #pragma unroll
        for (int j = 0; j < 8; j++) {
            int cc = c0 + j;
            if (r < cc) {
                float2 p = unpack2(acc[i][j]);
                float v = p.x + p.y;
                bool t = shC[r * Nn + cc] != 0;
                float sp = fmaxf(v, 0.f) + __logf(1.f + __expf(-fabsf(v)));
                lp += (t ? v : 0.f) - sp;
            }
        }
    }
    float tot = block_reduce16(lp);
    if (tid == 0) atomicAdd(&g_acc[0], tot);
}

// ---------------------------------------------------------------------------
__global__ void k_fin(float* out) {
    out[0] = (g_acc[1] - g_acc[0]) * (1.f / (float)Bg);
}

extern "C" void kernel_launch(void* const* d_in, const int* in_sizes, int n_in,
                              void* d_out, int out_size) {
    const float* x   = (const float*)d_in[0];
    const void*  ei  = d_in[1];
    const float* eps = (const float*)d_in[3];
    const float* W1  = (const float*)d_in[4];
    const float* b1  = (const float*)d_in[5];
    const float* Wmu = (const float*)d_in[6];
    const float* bmu = (const float*)d_in[7];
    const float* Wls = (const float*)d_in[8];
    const float* bls = (const float*)d_in[9];

    k_init<<<256, 256>>>(ei);
    k_prep<<<64, 256>>>(W1, Wmu, Wls);
    k_count<<<Ee / 256, 256>>>(ei);
    cudaFuncSetAttribute(k_enc, cudaFuncAttributeMaxDynamicSharedMemorySize, 212992);
    k_enc<<<Bg, 512, 212992>>>(x, b1, bmu, bls, eps);
    k_dec<<<Bg, 512>>>();
    k_fin<<<1, 1>>>((float*)d_out);
}

// round 14
// speedup vs baseline: 2.2872x; 2.2872x over previous
#include <cuda_runtime.h>

#define Bg 256
#define Nn 128
#define Dd 128
#define Ll 32
#define Ee 262144
#define BNt 32768

__device__ float    g_z[BNt * Ll];           // 4 MB latents
__device__ unsigned g_cnt[BNt * 32];         // 4 MB packed byte multiplicities
__device__ float    g_acc[2];                // [0]=sum log_probs, [1]=sum kls
__device__ int      g_is64;

// packed fp32 helpers ------------------------------------------------------
__device__ __forceinline__ void ffma2(unsigned long long& d,
                                      unsigned long long a, unsigned long long b) {
    asm("fma.rn.f32x2 %0, %1, %2, %3;" : "=l"(d) : "l"(a), "l"(b), "l"(d));
}
__device__ __forceinline__ float2 unpack2(unsigned long long v) {
    float lo, hi;
    asm("mov.b64 {%0, %1}, %2;" : "=f"(lo), "=f"(hi) : "l"(v));
    return make_float2(lo, hi);
}
__device__ __forceinline__ unsigned long long pack2(float lo, float hi) {
    unsigned long long r;
    asm("mov.b64 %0, {%1, %2};" : "=l"(r) : "f"(lo), "f"(hi));
    return r;
}
__device__ __forceinline__ unsigned long long dup2(float x) {
    unsigned long long r; unsigned u = __float_as_uint(x);
    asm("mov.b64 %0, {%1, %1};" : "=l"(r) : "r"(u));
    return r;
}

// ---------------------------------------------------------------------------
__global__ void k_init(const void* ei) {
    int i = blockIdx.x * blockDim.x + threadIdx.x;
    int stride = gridDim.x * blockDim.x;
    uint4 z4 = make_uint4(0u, 0u, 0u, 0u);
    for (int j = i; j < BNt * 32 / 4; j += stride) ((uint4*)g_cnt)[j] = z4;
    if (i < 2) g_acc[i] = 0.f;
    if (i == 0) {
        const int* e32 = (const int*)ei;
        int all0 = 1;
        #pragma unroll
        for (int t = 0; t < 32; t++) all0 &= (e32[2 * t + 1] == 0);
        g_is64 = all0;
    }
}

__device__ __forceinline__ void load_edge(const void* ei, int e, int& s, int& d) {
    if (g_is64) {
        s = (int)((const long long*)ei)[e];
        d = (int)((const long long*)ei)[Ee + e];
    } else {
        s = ((const int*)ei)[e];
        d = ((const int*)ei)[Ee + e];
    }
}

// per-edge multiplicity counts, packed 4 bytes/word (no-return atomics)
__global__ void k_count(const void* __restrict__ ei) {
    int e = blockIdx.x * blockDim.x + threadIdx.x;
    if (e >= Ee) return;
    int s, d; load_edge(ei, e, s, d);
    int b = s >> 7, li = s & (Nn - 1), lj = d & (Nn - 1);
    atomicAdd(&g_cnt[(b * Nn + li) * 32 + (lj >> 2)], 1u << (8 * (lj & 3)));
    atomicAdd(&g_cnt[(b * Nn + lj) * 32 + (li >> 2)], 1u << (8 * (li & 3)));
}

// block reduce (16 warps)
__device__ __forceinline__ float block_reduce16(float v) {
    __shared__ float sred[16];
    int lane = threadIdx.x & 31, w = threadIdx.x >> 5;
    #pragma unroll
    for (int o = 16; o; o >>= 1) v += __shfl_down_sync(0xffffffffu, v, o);
    if (lane == 0) sred[w] = v;
    __syncthreads();
    v = (threadIdx.x < 16) ? sred[threadIdx.x] : 0.f;
    if (w == 0) {
        #pragma unroll
        for (int o = 8; o; o >>= 1) v += __shfl_down_sync(0xffffffffu, v, o);
    }
    return v;  // valid in thread 0
}

// ---------------------------------------------------------------------------
// fused encoder: CTA = one graph (128 nodes), 512 threads, 208 KB smem.
// Row-pair-interleaved f32x2: A-operands broadcast LDS64, W-operands
// conflict-free lane-indexed float4 (natural k-major layout, no transpose).
//   shX : x tile          -> H2 (row-pair interleaved)
//   shW : W1 (k-major)    -> Wmu | Wls (natural layout)
//   shT2: T row-pair interleaved
//   shC : count table
// ---------------------------------------------------------------------------
__global__ void __launch_bounds__(512)
k_enc(const float* __restrict__ x, const float* __restrict__ W1,
      const float* __restrict__ b1, const float* __restrict__ Wmu,
      const float* __restrict__ bmu, const float* __restrict__ Wls,
      const float* __restrict__ bls, const float* __restrict__ eps) {
    extern __shared__ float sm[];
    float* shX  = sm;             // 16384 floats
    float* shW  = sm + 16384;     // 16384 floats
    float* shT2 = sm + 32768;     // 16384 floats
    unsigned* shC = (unsigned*)(sm + 49152);  // 4096 words
    const int tid = threadIdx.x;
    const int b = blockIdx.x;
    const int lane = tid & 31;
    const int wi = tid >> 5;      // 16 warps
    const int c0 = lane * 4;

    // load W1 (k-major, raw), x tile, count table — all independent
    {
        const float4* wg = (const float4*)W1;
        const float4* xg = (const float4*)(x + (size_t)b * Nn * Dd);
        const uint4*  cg = (const uint4*)g_cnt + b * 1024;
        float4* w4 = (float4*)shW;
        float4* x4 = (float4*)shX;
        uint4*  c4 = (uint4*)shC;
        for (int i = tid; i < 4096; i += 512) { w4[i] = wg[i]; x4[i] = xg[i]; }
        for (int i = tid; i < 1024; i += 512) c4[i] = cg[i];
    }
    __syncthreads();

    // gather: warp per node pair sequence (8 nodes/warp), multiplicity-weighted
    // write T row-pair interleaved: T2u[rp*128 + k] = (T[2rp][k], T[2rp+1][k])
    {
        const float4* x4 = (const float4*)shX;
        unsigned long long* T2u = (unsigned long long*)shT2;
        float accE[4];
        for (int t = 0; t < 8; t++) {
            int n = wi * 8 + t;
            float4 a = x4[n * 32 + lane];
            float acc[4] = {a.x, a.y, a.z, a.w};
            const uint4* cw4p = (const uint4*)&shC[n * 32];
            #pragma unroll 2
            for (int g = 0; g < 8; g++) {
                uint4 cv = cw4p[g];
                unsigned wv[4] = {cv.x, cv.y, cv.z, cv.w};
                #pragma unroll
                for (int j = 0; j < 4; j++) {
                    unsigned cw = wv[j];
                    if (!cw) continue;
                    int nb0 = (g * 4 + j) * 4;
                    #pragma unroll
                    for (int b4 = 0; b4 < 4; b4++) {
                        unsigned cnt = (cw >> (8 * b4)) & 255u;
                        if (cnt) {
                            float fc = (float)cnt;
                            float4 xv = x4[(nb0 + b4) * 32 + lane];
                            acc[0] += fc * xv.x; acc[1] += fc * xv.y;
                            acc[2] += fc * xv.z; acc[3] += fc * xv.w;
                        }
                    }
                }
            }
            if ((t & 1) == 0) {
                accE[0] = acc[0]; accE[1] = acc[1]; accE[2] = acc[2]; accE[3] = acc[3];
            } else {
                int rp = n >> 1;
                #pragma unroll
                for (int kk = 0; kk < 4; kk++)
                    T2u[rp * 128 + c0 + kk] = pack2(accE[kk], acc[kk]);
            }
        }
    }
    __syncthreads();

    // phase1: H = relu(T @ W1 + b1). warp = 4 row-pairs, lane = 4 cols.
    {
        const int rpb = wi * 4;
        const unsigned long long* T2u = (const unsigned long long*)shT2;
        unsigned long long acc2[4][4];
        #pragma unroll
        for (int rp = 0; rp < 4; rp++)
            #pragma unroll
            for (int cc = 0; cc < 4; cc++) acc2[rp][cc] = 0ull;

        #pragma unroll 4
        for (int k = 0; k < 128; k++) {
            float4 w4 = *(const float4*)&shW[k * 128 + c0];  // conflict-free
            unsigned long long dw0 = dup2(w4.x), dw1 = dup2(w4.y);
            unsigned long long dw2 = dup2(w4.z), dw3 = dup2(w4.w);
            #pragma unroll
            for (int rp = 0; rp < 4; rp++) {
                unsigned long long a2 = T2u[(rpb + rp) * 128 + k];  // broadcast
                ffma2(acc2[rp][0], a2, dw0);
                ffma2(acc2[rp][1], a2, dw1);
                ffma2(acc2[rp][2], a2, dw2);
                ffma2(acc2[rp][3], a2, dw3);
            }
        }
        float4 bb = *(const float4*)(b1 + c0);
        float bv[4] = {bb.x, bb.y, bb.z, bb.w};
        unsigned long long* H2u = (unsigned long long*)shX;
        #pragma unroll
        for (int rp = 0; rp < 4; rp++)
            #pragma unroll
            for (int cc = 0; cc < 4; cc++) {
                float2 p = unpack2(acc2[rp][cc]);
                float h0 = fmaxf(p.x + bv[cc], 0.f);
                float h1 = fmaxf(p.y + bv[cc], 0.f);
                H2u[(rpb + rp) * 128 + c0 + cc] = pack2(h0, h1);
            }
    }
    __syncthreads();

    // load Wmu | Wls (natural [k*32+l] layout) over W1
    {
        const float4* wm = (const float4*)Wmu;
        const float4* wl = (const float4*)Wls;
        float4* w4 = (float4*)shW;
        for (int i = tid; i < 1024; i += 512) {
            w4[i]        = wm[i];
            w4[1024 + i] = wl[i];
        }
    }
    __syncthreads();

    // phase2: warp = 4 row-pairs, lane = latent l. mu/ls via row-pair FFMA2.
    float klp = 0.f;
    {
        const int l = lane;
        const int rpb = wi * 4;
        const float* shWm = shW;
        const float* shWl = shW + 4096;
        const unsigned long long* H2u = (const unsigned long long*)shX;
        unsigned long long accm[4], accl[4];
        #pragma unroll
        for (int rp = 0; rp < 4; rp++) { accm[rp] = 0ull; accl[rp] = 0ull; }

        #pragma unroll 4
        for (int k = 0; k < 128; k++) {
            unsigned long long dm = dup2(shWm[k * 32 + l]);  // conflict-free
            unsigned long long dl = dup2(shWl[k * 32 + l]);
            #pragma unroll
            for (int rp = 0; rp < 4; rp++) {
                unsigned long long h2 = H2u[(rpb + rp) * 128 + k];  // broadcast
                ffma2(accm[rp], h2, dm);
                ffma2(accl[rp], h2, dl);
            }
        }
        float bm = bmu[l], bl = bls[l];
        #pragma unroll
        for (int rp = 0; rp < 4; rp++) {
            int r0 = (rpb + rp) * 2;
            int row0 = b * Nn + r0;
            float2 pm = unpack2(accm[rp]);
            float2 pl = unpack2(accl[rp]);
            float m0 = pm.x + bm, m1 = pm.y + bm;
            float s0 = pl.x + bl, s1 = pl.y + bl;
            float st0 = __expf(s0), st1 = __expf(s1);
            g_z[row0 * Ll + l]       = m0 + st0 * eps[row0 * Ll + l];
            g_z[(row0 + 1) * Ll + l] = m1 + st1 * eps[(row0 + 1) * Ll + l];
            klp += 0.5f * (st0 * st0 + m0 * m0 - 1.f - 2.f * s0)
                 + 0.5f * (st1 * st1 + m1 * m1 - 1.f - 2.f * s1);
        }
    }
    float tot = block_reduce16(klp);
    if (tid == 0) atomicAdd(&g_acc[1], tot);
}

// ---------------------------------------------------------------------------
// decoder: CTA = graph, 512 threads, f32x2 gram; targets = (count != 0)
// ---------------------------------------------------------------------------
__global__ void __launch_bounds__(512) k_dec() {
    __shared__ float shZ[Nn * 32];
    __shared__ unsigned char shC[Nn * Nn];   // 16KB count bytes
    const int tid = threadIdx.x;
    const int b = blockIdx.x;

    {
        const float4* zg = (const float4*)(g_z + (size_t)b * Nn * Ll);
        float4* z4 = (float4*)shZ;
        for (int j = tid; j < 1024; j += 512) {
            int n = j >> 3, k4 = j & 7;
            z4[n * 8 + ((k4 + (n >> 3)) & 7)] = zg[j];
        }
        const uint4* cg = (const uint4*)g_cnt + b * 1024;
        uint4* c4 = (uint4*)shC;
        for (int i = tid; i < 1024; i += 512) c4[i] = cg[i];
    }
    __syncthreads();

    const int tx = tid & 15, ty = tid >> 4;
    const int r0 = ty * 4, c0 = tx * 8;
    const int rota = ty >> 1;
    const ulonglong2* z2 = (const ulonglong2*)shZ;

    unsigned long long acc[4][8];
    #pragma unroll
    for (int i = 0; i < 4; i++)
        #pragma unroll
        for (int j = 0; j < 8; j++) acc[i][j] = 0ull;

    #pragma unroll
    for (int k4 = 0; k4 < 8; k4++) {
        ulonglong2 bb[8];
        int gb = (k4 + tx) & 7;
        #pragma unroll
        for (int j = 0; j < 8; j++) bb[j] = z2[(c0 + j) * 8 + gb];
        int ga = (k4 + rota) & 7;
        #pragma unroll
        for (int i = 0; i < 4; i++) {
            ulonglong2 a2 = z2[(r0 + i) * 8 + ga];
            #pragma unroll
            for (int j = 0; j < 8; j++) {
                ffma2(acc[i][j], a2.x, bb[j].x);
                ffma2(acc[i][j], a2.y, bb[j].y);
            }
        }
    }

    float lp = 0.f;
    #pragma unroll
    for (int i = 0; i < 4; i++) {
        int r = r0 + i;
        #pragma unroll
        for (int j = 0; j < 8; j++) {
            int cc = c0 + j;
            if (r < cc) {
                float2 p = unpack2(acc[i][j]);
                float v = p.x + p.y;
                bool t = shC[r * Nn + cc] != 0;
                float sp = fmaxf(v, 0.f) + __logf(1.f + __expf(-fabsf(v)));
                lp += (t ? v : 0.f) - sp;
            }
        }
    }
    float tot = block_reduce16(lp);
    if (tid == 0) atomicAdd(&g_acc[0], tot);
}

// ---------------------------------------------------------------------------
__global__ void k_fin(float* out) {
    out[0] = (g_acc[1] - g_acc[0]) * (1.f / (float)Bg);
}

extern "C" void kernel_launch(void* const* d_in, const int* in_sizes, int n_in,
                              void* d_out, int out_size) {
    const float* x   = (const float*)d_in[0];
    const void*  ei  = d_in[1];
    const float* eps = (const float*)d_in[3];
    const float* W1  = (const float*)d_in[4];
    const float* b1  = (const float*)d_in[5];
    const float* Wmu = (const float*)d_in[6];
    const float* bmu = (const float*)d_in[7];
    const float* Wls = (const float*)d_in[8];
    const float* bls = (const float*)d_in[9];

    k_init<<<256, 256>>>(ei);
    k_count<<<Ee / 256, 256>>>(ei);
    cudaFuncSetAttribute(k_enc, cudaFuncAttributeMaxDynamicSharedMemorySize, 212992);
    k_enc<<<Bg, 512, 212992>>>(x, W1, b1, Wmu, bmu, Wls, bls, eps);
    k_dec<<<Bg, 512>>>();
    k_fin<<<1, 1>>>((float*)d_out);
}

// round 16
// speedup vs baseline: 2.5013x; 1.0936x over previous
#include <cuda_runtime.h>

#define Bg 256
#define Nn 128
#define Dd 128
#define Ll 32
#define Ee 262144
#define BNt 32768

__device__ unsigned g_cnt[BNt * 32];         // 4 MB packed byte multiplicities
__device__ float    g_acc[1];                // sum over graphs of (kl - log_prob)
__device__ int      g_is64;

// packed fp32 helpers ------------------------------------------------------
__device__ __forceinline__ void ffma2(unsigned long long& d,
                                      unsigned long long a, unsigned long long b) {
    asm("fma.rn.f32x2 %0, %1, %2, %3;" : "=l"(d) : "l"(a), "l"(b), "l"(d));
}
__device__ __forceinline__ float2 unpack2(unsigned long long v) {
    float lo, hi;
    asm("mov.b64 {%0, %1}, %2;" : "=f"(lo), "=f"(hi) : "l"(v));
    return make_float2(lo, hi);
}
__device__ __forceinline__ unsigned long long pack2(float lo, float hi) {
    unsigned long long r;
    asm("mov.b64 %0, {%1, %2};" : "=l"(r) : "f"(lo), "f"(hi));
    return r;
}
__device__ __forceinline__ unsigned long long dup2(float x) {
    unsigned long long r; unsigned u = __float_as_uint(x);
    asm("mov.b64 %0, {%1, %1};" : "=l"(r) : "r"(u));
    return r;
}

// ---------------------------------------------------------------------------
__global__ void k_init(const void* ei) {
    int i = blockIdx.x * blockDim.x + threadIdx.x;
    int stride = gridDim.x * blockDim.x;
    uint4 z4 = make_uint4(0u, 0u, 0u, 0u);
    for (int j = i; j < BNt * 32 / 4; j += stride) ((uint4*)g_cnt)[j] = z4;
    if (i == 0) {
        g_acc[0] = 0.f;
        const int* e32 = (const int*)ei;
        int all0 = 1;
        #pragma unroll
        for (int t = 0; t < 32; t++) all0 &= (e32[2 * t + 1] == 0);
        g_is64 = all0;
    }
}

__device__ __forceinline__ void load_edge(const void* ei, int e, int& s, int& d) {
    if (g_is64) {
        s = (int)((const long long*)ei)[e];
        d = (int)((const long long*)ei)[Ee + e];
    } else {
        s = ((const int*)ei)[e];
        d = ((const int*)ei)[Ee + e];
    }
}

// per-edge multiplicity counts, packed 4 bytes/word (no-return atomics)
__global__ void k_count(const void* __restrict__ ei) {
    int e = blockIdx.x * blockDim.x + threadIdx.x;
    if (e >= Ee) return;
    int s, d; load_edge(ei, e, s, d);
    int b = s >> 7, li = s & (Nn - 1), lj = d & (Nn - 1);
    atomicAdd(&g_cnt[(b * Nn + li) * 32 + (lj >> 2)], 1u << (8 * (lj & 3)));
    atomicAdd(&g_cnt[(b * Nn + lj) * 32 + (li >> 2)], 1u << (8 * (li & 3)));
}

// block reduce (16 warps)
__device__ __forceinline__ float block_reduce16(float v) {
    __shared__ float sred[16];
    int lane = threadIdx.x & 31, w = threadIdx.x >> 5;
    #pragma unroll
    for (int o = 16; o; o >>= 1) v += __shfl_down_sync(0xffffffffu, v, o);
    if (lane == 0) sred[w] = v;
    __syncthreads();
    v = (threadIdx.x < 16) ? sred[threadIdx.x] : 0.f;
    if (w == 0) {
        #pragma unroll
        for (int o = 8; o; o >>= 1) v += __shfl_down_sync(0xffffffffu, v, o);
    }
    return v;  // valid in thread 0
}

// ---------------------------------------------------------------------------
// fully fused per-graph kernel: gather -> GEMM1 -> mu/ls -> z -> gram ->
// bernoulli log-prob + KL, one CTA per graph, 512 threads, 208 KB smem.
//   shX : x tile            -> H2 (row-pair interleaved)
//   shW : W1 (k-major)      -> Wmu | Wls
//   shT2: T row-pair interl -> z (dec-swizzled)
//   shC : count table (also provides decoder targets)
// ---------------------------------------------------------------------------
__global__ void __launch_bounds__(512)
k_fused(const float* __restrict__ x, const float* __restrict__ W1,
        const float* __restrict__ b1, const float* __restrict__ Wmu,
        const float* __restrict__ bmu, const float* __restrict__ Wls,
        const float* __restrict__ bls, const float* __restrict__ eps) {
    extern __shared__ float sm[];
    float* shX  = sm;             // 16384 floats
    float* shW  = sm + 16384;     // 16384 floats
    float* shT2 = sm + 32768;     // 16384 floats
    unsigned* shC = (unsigned*)(sm + 49152);  // 4096 words
    const int tid = threadIdx.x;
    const int b = blockIdx.x;
    const int lane = tid & 31;
    const int wi = tid >> 5;      // 16 warps
    const int c0 = lane * 4;

    // load W1 (k-major, raw), x tile, count table — all independent
    {
        const float4* wg = (const float4*)W1;
        const float4* xg = (const float4*)(x + (size_t)b * Nn * Dd);
        const uint4*  cg = (const uint4*)g_cnt + b * 1024;
        float4* w4 = (float4*)shW;
        float4* x4 = (float4*)shX;
        uint4*  c4 = (uint4*)shC;
        for (int i = tid; i < 4096; i += 512) { w4[i] = wg[i]; x4[i] = xg[i]; }
        for (int i = tid; i < 1024; i += 512) c4[i] = cg[i];
    }
    __syncthreads();

    // gather: warp per 8 nodes, multiplicity-weighted
    // write T row-pair interleaved: T2u[rp*128 + k] = (T[2rp][k], T[2rp+1][k])
    {
        const float4* x4 = (const float4*)shX;
        unsigned long long* T2u = (unsigned long long*)shT2;
        float accE[4];
        for (int t = 0; t < 8; t++) {
            int n = wi * 8 + t;
            float4 a = x4[n * 32 + lane];
            float acc[4] = {a.x, a.y, a.z, a.w};
            const uint4* cw4p = (const uint4*)&shC[n * 32];
            #pragma unroll 2
            for (int g = 0; g < 8; g++) {
                uint4 cv = cw4p[g];
                unsigned wv[4] = {cv.x, cv.y, cv.z, cv.w};
                #pragma unroll
                for (int j = 0; j < 4; j++) {
                    unsigned cw = wv[j];
                    if (!cw) continue;
                    int nb0 = (g * 4 + j) * 4;
                    #pragma unroll
                    for (int b4 = 0; b4 < 4; b4++) {
                        unsigned cnt = (cw >> (8 * b4)) & 255u;
                        if (cnt) {
                            float fc = (float)cnt;
                            float4 xv = x4[(nb0 + b4) * 32 + lane];
                            acc[0] += fc * xv.x; acc[1] += fc * xv.y;
                            acc[2] += fc * xv.z; acc[3] += fc * xv.w;
                        }
                    }
                }
            }
            if ((t & 1) == 0) {
                accE[0] = acc[0]; accE[1] = acc[1]; accE[2] = acc[2]; accE[3] = acc[3];
            } else {
                int rp = n >> 1;
                #pragma unroll
                for (int kk = 0; kk < 4; kk++)
                    T2u[rp * 128 + c0 + kk] = pack2(accE[kk], acc[kk]);
            }
        }
    }
    __syncthreads();

    // phase1: H = relu(T @ W1 + b1). warp = 4 row-pairs, lane = 4 cols.
    {
        const int rpb = wi * 4;
        const unsigned long long* T2u = (const unsigned long long*)shT2;
        unsigned long long acc2[4][4];
        #pragma unroll
        for (int rp = 0; rp < 4; rp++)
            #pragma unroll
            for (int cc = 0; cc < 4; cc++) acc2[rp][cc] = 0ull;

        #pragma unroll 4
        for (int k = 0; k < 128; k++) {
            float4 w4 = *(const float4*)&shW[k * 128 + c0];  // conflict-free
            unsigned long long dw0 = dup2(w4.x), dw1 = dup2(w4.y);
            unsigned long long dw2 = dup2(w4.z), dw3 = dup2(w4.w);
            #pragma unroll
            for (int rp = 0; rp < 4; rp++) {
                unsigned long long a2 = T2u[(rpb + rp) * 128 + k];  // broadcast
                ffma2(acc2[rp][0], a2, dw0);
                ffma2(acc2[rp][1], a2, dw1);
                ffma2(acc2[rp][2], a2, dw2);
                ffma2(acc2[rp][3], a2, dw3);
            }
        }
        float4 bb = *(const float4*)(b1 + c0);
        float bv[4] = {bb.x, bb.y, bb.z, bb.w};
        unsigned long long* H2u = (unsigned long long*)shX;
        __syncthreads();   // T2u reads done before H overwrites shX? (H->shX, T2->shT2: distinct; sync protects W reload below)
        #pragma unroll
        for (int rp = 0; rp < 4; rp++)
            #pragma unroll
            for (int cc = 0; cc < 4; cc++) {
                float2 p = unpack2(acc2[rp][cc]);
                float h0 = fmaxf(p.x + bv[cc], 0.f);
                float h1 = fmaxf(p.y + bv[cc], 0.f);
                H2u[(rpb + rp) * 128 + c0 + cc] = pack2(h0, h1);
            }
    }
    __syncthreads();

    // load Wmu | Wls (natural [k*32+l] layout) over W1
    {
        const float4* wm = (const float4*)Wmu;
        const float4* wl = (const float4*)Wls;
        float4* w4 = (float4*)shW;
        for (int i = tid; i < 1024; i += 512) {
            w4[i]        = wm[i];
            w4[1024 + i] = wl[i];
        }
    }
    __syncthreads();

    // phase2: warp = 4 row-pairs, lane = latent l; z stored to shT2 in
    // dec-swizzled layout: float addr = (n*8 + ((l>>2)+(n>>3) & 7))*4 + (l&3)
    float klp = 0.f;
    {
        const int l = lane;
        const int rpb = wi * 4;
        const float* shWm = shW;
        const float* shWl = shW + 4096;
        const unsigned long long* H2u = (const unsigned long long*)shX;
        unsigned long long accm[4], accl[4];
        #pragma unroll
        for (int rp = 0; rp < 4; rp++) { accm[rp] = 0ull; accl[rp] = 0ull; }

        #pragma unroll 4
        for (int k = 0; k < 128; k++) {
            unsigned long long dm = dup2(shWm[k * 32 + l]);  // conflict-free
            unsigned long long dl = dup2(shWl[k * 32 + l]);
            #pragma unroll
            for (int rp = 0; rp < 4; rp++) {
                unsigned long long h2 = H2u[(rpb + rp) * 128 + k];  // broadcast
                ffma2(accm[rp], h2, dm);
                ffma2(accl[rp], h2, dl);
            }
        }
        float bm = bmu[l], bl = bls[l];
        const int kg = l >> 2, ko = l & 3;
        #pragma unroll
        for (int rp = 0; rp < 4; rp++) {
            int r0 = (rpb + rp) * 2;
            int row0 = b * Nn + r0;
            float2 pm = unpack2(accm[rp]);
            float2 pl = unpack2(accl[rp]);
            float m0 = pm.x + bm, m1 = pm.y + bm;
            float s0 = pl.x + bl, s1 = pl.y + bl;
            float st0 = __expf(s0), st1 = __expf(s1);
            float z0 = m0 + st0 * eps[row0 * Ll + l];
            float z1 = m1 + st1 * eps[(row0 + 1) * Ll + l];
            // conflict-free swizzled scalar stores (all 32 banks per row)
            shT2[(r0 * 8 + ((kg + (r0 >> 3)) & 7)) * 4 + ko] = z0;
            int r1 = r0 + 1;
            shT2[(r1 * 8 + ((kg + (r1 >> 3)) & 7)) * 4 + ko] = z1;
            klp += 0.5f * (st0 * st0 + m0 * m0 - 1.f - 2.f * s0)
                 + 0.5f * (st1 * st1 + m1 * m1 - 1.f - 2.f * s1);
        }
    }
    __syncthreads();

    // decoder: gram = Z Z^T from shT2; targets = count byte != 0 (shC)
    float lp = 0.f;
    {
        const unsigned char* cb = (const unsigned char*)shC;
        const int tx = tid & 15, ty = tid >> 4;
        const int r0 = ty * 4, cc0 = tx * 8;
        const int rota = ty >> 1;
        const ulonglong2* z2 = (const ulonglong2*)shT2;

        unsigned long long acc[4][8];
        #pragma unroll
        for (int i = 0; i < 4; i++)
            #pragma unroll
            for (int j = 0; j < 8; j++) acc[i][j] = 0ull;

        #pragma unroll
        for (int k4 = 0; k4 < 8; k4++) {
            ulonglong2 bb[8];
            int gb = (k4 + tx) & 7;
            #pragma unroll
            for (int j = 0; j < 8; j++) bb[j] = z2[(cc0 + j) * 8 + gb];
            int ga = (k4 + rota) & 7;
            #pragma unroll
            for (int i = 0; i < 4; i++) {
                ulonglong2 a2 = z2[(r0 + i) * 8 + ga];
                #pragma unroll
                for (int j = 0; j < 8; j++) {
                    ffma2(acc[i][j], a2.x, bb[j].x);
                    ffma2(acc[i][j], a2.y, bb[j].y);
                }
            }
        }

        #pragma unroll
        for (int i = 0; i < 4; i++) {
            int r = r0 + i;
            #pragma unroll
            for (int j = 0; j < 8; j++) {
                int cc = cc0 + j;
                if (r < cc) {
                    float2 p = unpack2(acc[i][j]);
                    float v = p.x + p.y;
                    bool t = cb[r * Nn + cc] != 0;
                    float sp = fmaxf(v, 0.f) + __logf(1.f + __expf(-fabsf(v)));
                    lp += (t ? v : 0.f) - sp;
                }
            }
        }
    }

    float tot = block_reduce16(klp - lp);
    if (tid == 0) atomicAdd(&g_acc[0], tot);
}

// ---------------------------------------------------------------------------
__global__ void k_fin(float* out) {
    out[0] = g_acc[0] * (1.f / (float)Bg);
}

extern "C" void kernel_launch(void* const* d_in, const int* in_sizes, int n_in,
                              void* d_out, int out_size) {
    const float* x   = (const float*)d_in[0];
    const void*  ei  = d_in[1];
    const float* eps = (const float*)d_in[3];
    const float* W1  = (const float*)d_in[4];
    const float* b1  = (const float*)d_in[5];
    const float* Wmu = (const float*)d_in[6];
    const float* bmu = (const float*)d_in[7];
    const float* Wls = (const float*)d_in[8];
    const float* bls = (const float*)d_in[9];

    k_init<<<256, 256>>>(ei);
    k_count<<<Ee / 256, 256>>>(ei);
    cudaFuncSetAttribute(k_fused, cudaFuncAttributeMaxDynamicSharedMemorySize, 212992);
    k_fused<<<Bg, 512, 212992>>>(x, W1, b1, Wmu, bmu, Wls, bls, eps);
    k_fin<<<1, 1>>>((float*)d_out);
}